// round 5
// baseline (speedup 1.0000x reference)
#include <cuda_runtime.h>
#include <cuda_bf16.h>
#include <math.h>
#include <stdint.h>

#define BB 32
#define TF 2048
#define TP 256
#define FD 768
#define PD 512
#define AD 512
typedef __nv_bfloat16 bf16;
typedef __nv_bfloat162 bf162;

// ---------------- device scratch ----------------
__device__ float g_q[(size_t)BB * TF * AD];
__device__ bf16 g_f_hi[(size_t)BB * TF * FD], g_f_lo[(size_t)BB * TF * FD];
__device__ bf16 g_p_hi[(size_t)BB * TP * PD], g_p_lo[(size_t)BB * TP * PD];
__device__ bf16 g_wqt_hi[AD * FD], g_wqt_lo[AD * FD];
__device__ bf16 g_wkt_hi[AD * PD], g_wkt_lo[AD * PD];
__device__ bf16 g_q_hi[(size_t)BB * TF * AD], g_q_lo[(size_t)BB * TF * AD];
__device__ bf16 g_k_hi[(size_t)BB * TP * AD], g_k_lo[(size_t)BB * TP * AD];
__device__ bf16 g_kt_hi[(size_t)BB * AD * TP], g_kt_lo[(size_t)BB * AD * TP];
__device__ bf16 g_P_hi[(size_t)BB * TF * TP], g_P_lo[(size_t)BB * TF * TP];

// ---------------- helpers ----------------
__device__ __forceinline__ uint32_t s2u(const void* p) {
    uint32_t a;
    asm("{ .reg .u64 t; cvta.to.shared.u64 t, %1; cvt.u32.u64 %0, t; }"
        : "=r"(a) : "l"(p));
    return a;
}
__device__ __forceinline__ void split1(float v, bf16& h, bf16& l) {
    h = __float2bfloat16_rn(v);
    l = __float2bfloat16_rn(v - __bfloat162float(h));
}
__device__ __forceinline__ void cp16(uint32_t dst, const void* src) {
    asm volatile("cp.async.cg.shared.global [%0], [%1], 16;" :: "r"(dst), "l"(src));
}
__device__ __forceinline__ void cp_commit() { asm volatile("cp.async.commit_group;"); }
template <int N>
__device__ __forceinline__ void cp_wait() {
    asm volatile("cp.async.wait_group %0;" :: "n"(N));
}
__device__ __forceinline__ void ldm4(uint32_t* r, uint32_t addr) {
    asm volatile("ldmatrix.sync.aligned.m8n8.x4.shared.b16 {%0,%1,%2,%3}, [%4];"
                 : "=r"(r[0]), "=r"(r[1]), "=r"(r[2]), "=r"(r[3]) : "r"(addr));
}
__device__ __forceinline__ void mma16816(float* c, const uint32_t* a,
                                         uint32_t b0, uint32_t b1) {
    asm volatile("mma.sync.aligned.m16n8k16.row.col.f32.bf16.bf16.f32 "
                 "{%0,%1,%2,%3}, {%4,%5,%6,%7}, {%8,%9}, {%0,%1,%2,%3};"
                 : "+f"(c[0]), "+f"(c[1]), "+f"(c[2]), "+f"(c[3])
                 : "r"(a[0]), "r"(a[1]), "r"(a[2]), "r"(a[3]), "r"(b0), "r"(b1));
}
// FFMA-only exp (no MUFU); valid for x <= ~80, clamps hard-underflow to ~0.
__device__ __forceinline__ float fexp(float x) {
    float y = fmaxf(x * 1.44269504f, -125.0f);
    float i = rintf(y);
    float f = y - i;
    float p = 1.3333558146e-3f;
    p = fmaf(p, f, 9.6181291076e-3f);
    p = fmaf(p, f, 5.5504108664e-2f);
    p = fmaf(p, f, 2.4022650696e-1f);
    p = fmaf(p, f, 6.9314718056e-1f);
    p = fmaf(p, f, 1.0f);
    float s = __int_as_float(((int)i + 127) << 23);
    return p * s;
}
// cp.async [ROWS x 64] bf16 K-major tile into XOR-swizzled smem (128B rows)
template <int ROWS>
__device__ __forceinline__ void ldt(const bf16* __restrict__ src, size_t row0,
                                    int ld, int k0, uint32_t dst, int t) {
#pragma unroll
    for (int it = 0; it < ROWS / 32; it++) {
        int u = it * 256 + t;
        int row = u >> 3, q = u & 7;
        cp16(dst + row * 128 + ((q ^ (row & 7)) << 4),
             src + (row0 + row) * (size_t)ld + k0 + q * 8);
    }
}

// ================= gemm128: C[128,256] = A[128,K] @ B[256,K]^T ==============
// MODE 0: projQ (+bias -> g_q, g_q_hi/lo)   grid(2, Mtiles)
// MODE 1: projK (+bias -> g_k_hi/lo + g_kt) grid(2, Mtiles)
// MODE 2: energy (+mask, softmax -> energy_out + g_P_hi/lo) grid(16, B)
#define STG   98304            // per-stage: Ah 16K | Al 16K | Bh 32K | Bl 32K
#define SMEM_G (2 * STG + 2048)
template <int MODE>
__global__ __launch_bounds__(256)
void gemm128(const bf16* __restrict__ Ah, const bf16* __restrict__ Al, int lda,
             const bf16* __restrict__ Bh, const bf16* __restrict__ Bl, int ldb,
             int K, const void* __restrict__ aux, float* __restrict__ outp) {
    extern __shared__ char sm[];
    const uint32_t sb0 = s2u(sm);
    const int t = threadIdx.x, lane = t & 31, wid = t >> 5;
    const int wm = wid >> 1, wn = wid & 1;
    const int bx = blockIdx.x, by = blockIdx.y;
    float* aux_s = (float*)(sm + 2 * STG);

    size_t arow0, brow0;
    if (MODE == 2) {
        arow0 = (size_t)by * TF + (size_t)bx * 128;
        brow0 = (size_t)by * TP;
        const int* am = (const int*)aux;
        aux_s[t] = (1.0f - (float)am[by * TP + t]) * (-1000.0f);
    } else {
        arow0 = (size_t)by * 128;
        brow0 = (size_t)bx * 256;
        aux_s[t] = ((const float*)aux)[bx * 256 + t];
    }
    const int NC = K / 64;

    float acc[2][16][4];
#pragma unroll
    for (int mt = 0; mt < 2; mt++)
#pragma unroll
        for (int nt = 0; nt < 16; nt++)
#pragma unroll
            for (int j = 0; j < 4; j++) acc[mt][nt][j] = 0.0f;

    {
        uint32_t s0 = sb0;
        ldt<128>(Ah, arow0, lda, 0, s0, t);
        ldt<128>(Al, arow0, lda, 0, s0 + 16384, t);
        ldt<256>(Bh, brow0, ldb, 0, s0 + 32768, t);
        ldt<256>(Bl, brow0, ldb, 0, s0 + 65536, t);
        cp_commit();
    }
    for (int c = 0; c < NC; c++) {
        if (c + 1 < NC) {
            uint32_t sn = sb0 + ((c + 1) & 1) * STG;
            const int k0 = (c + 1) * 64;
            ldt<128>(Ah, arow0, lda, k0, sn, t);
            ldt<128>(Al, arow0, lda, k0, sn + 16384, t);
            ldt<256>(Bh, brow0, ldb, k0, sn + 32768, t);
            ldt<256>(Bl, brow0, ldb, k0, sn + 65536, t);
            cp_commit();
            cp_wait<1>();
        } else {
            cp_wait<0>();
        }
        __syncthreads();
        const uint32_t s = sb0 + (c & 1) * STG;
#pragma unroll
        for (int ks = 0; ks < 4; ks++) {
            uint32_t ah[2][4], al[2][4];
#pragma unroll
            for (int mt = 0; mt < 2; mt++) {
                int row = wm * 32 + mt * 16 + (lane & 15);
                int q = ks * 2 + (lane >> 4);
                uint32_t off = row * 128 + ((q ^ (row & 7)) << 4);
                ldm4(ah[mt], s + off);
                ldm4(al[mt], s + 16384 + off);
            }
#pragma unroll
            for (int h = 0; h < 2; h++) {
                const int g = lane >> 3, w = lane & 7;
                uint32_t bb[8][2];
#pragma unroll
                for (int np = 0; np < 4; np++) {
                    int ntl = h * 8 + np * 2 + (g >> 1);
                    int row = wn * 128 + ntl * 8 + w;
                    int q = ks * 2 + (g & 1);
                    uint32_t off = row * 128 + ((q ^ (row & 7)) << 4);
                    uint32_t r4[4];
                    ldm4(r4, s + 32768 + off);
                    bb[np * 2][0] = r4[0]; bb[np * 2][1] = r4[1];
                    bb[np * 2 + 1][0] = r4[2]; bb[np * 2 + 1][1] = r4[3];
                }
#pragma unroll
                for (int mt = 0; mt < 2; mt++)
#pragma unroll
                    for (int nt = 0; nt < 8; nt++) {
                        mma16816(acc[mt][h * 8 + nt], ah[mt], bb[nt][0], bb[nt][1]);
                        mma16816(acc[mt][h * 8 + nt], al[mt], bb[nt][0], bb[nt][1]);
                    }
#pragma unroll
                for (int np = 0; np < 4; np++) {
                    int ntl = h * 8 + np * 2 + (g >> 1);
                    int row = wn * 128 + ntl * 8 + w;
                    int q = ks * 2 + (g & 1);
                    uint32_t off = row * 128 + ((q ^ (row & 7)) << 4);
                    uint32_t r4[4];
                    ldm4(r4, s + 65536 + off);
                    bb[np * 2][0] = r4[0]; bb[np * 2][1] = r4[1];
                    bb[np * 2 + 1][0] = r4[2]; bb[np * 2 + 1][1] = r4[3];
                }
#pragma unroll
                for (int mt = 0; mt < 2; mt++)
#pragma unroll
                    for (int nt = 0; nt < 8; nt++)
                        mma16816(acc[mt][h * 8 + nt], ah[mt], bb[nt][0], bb[nt][1]);
            }
        }
        __syncthreads();
    }

    // ---------------- epilogues ----------------
    if (MODE == 0 || MODE == 1) {
#pragma unroll
        for (int mt = 0; mt < 2; mt++)
#pragma unroll
            for (int hh = 0; hh < 2; hh++) {
                const int rl = wm * 32 + mt * 16 + (lane >> 2) + hh * 8;
                const size_t gr = (size_t)by * 128 + rl;
#pragma unroll
                for (int nt = 0; nt < 16; nt++) {
                    const int cl = wn * 128 + nt * 8 + (lane & 3) * 2;
                    float v0 = acc[mt][nt][hh * 2] + aux_s[cl];
                    float v1 = acc[mt][nt][hh * 2 + 1] + aux_s[cl + 1];
                    const int gc = bx * 256 + cl;
                    bf16 h0, l0, h1, l1;
                    split1(v0, h0, l0);
                    split1(v1, h1, l1);
                    bf162 ph; ph.x = h0; ph.y = h1;
                    bf162 pl; pl.x = l0; pl.y = l1;
                    if (MODE == 0) {
                        *(float2*)&g_q[gr * AD + gc] = make_float2(v0, v1);
                        *(bf162*)&g_q_hi[gr * AD + gc] = ph;
                        *(bf162*)&g_q_lo[gr * AD + gc] = pl;
                    } else {
                        *(bf162*)&g_k_hi[gr * AD + gc] = ph;
                        *(bf162*)&g_k_lo[gr * AD + gc] = pl;
                        const int b = (int)(gr >> 8), p = (int)(gr & 255);
                        g_kt_hi[((size_t)b * AD + gc) * TP + p] = h0;
                        g_kt_lo[((size_t)b * AD + gc) * TP + p] = l0;
                        g_kt_hi[((size_t)b * AD + gc + 1) * TP + p] = h1;
                        g_kt_lo[((size_t)b * AD + gc + 1) * TP + p] = l1;
                    }
                }
            }
    } else {
        // masked energy -> smem E[128][264], energy out, softmax, P hi/lo
        float* E = (float*)sm;
        float* minv = (float*)(sm + 136192);
#pragma unroll
        for (int mt = 0; mt < 2; mt++)
#pragma unroll
            for (int hh = 0; hh < 2; hh++) {
                const int rl = wm * 32 + mt * 16 + (lane >> 2) + hh * 8;
#pragma unroll
                for (int nt = 0; nt < 16; nt++) {
                    const int cl = wn * 128 + nt * 8 + (lane & 3) * 2;
                    float v0 = acc[mt][nt][hh * 2] + aux_s[cl];
                    float v1 = acc[mt][nt][hh * 2 + 1] + aux_s[cl + 1];
                    *(float2*)&E[rl * 264 + cl] = make_float2(v0, v1);
                }
            }
        __syncthreads();
        const size_t growE = arow0;
        {
            const int row = t >> 1, cb = (t & 1) * 128;
            const float* src = E + row * 264 + cb;
            float* dst = outp + (growE + row) * TP + cb;
#pragma unroll 8
            for (int j = 0; j < 32; j++) *(float4*)(dst + j * 4) = *(const float4*)(src + j * 4);
        }
        if (t < 128) {
            float* row = E + t * 264;
            float mx = -1e30f;
#pragma unroll 8
            for (int j = 0; j < 256; j++) mx = fmaxf(mx, row[j]);
            float ssum = 0.0f;
#pragma unroll 8
            for (int j = 0; j < 256; j++) {
                float v = fexp(row[j] - mx);
                row[j] = v;
                ssum += v;
            }
            minv[t] = 1.0f / ssum;
        }
        __syncthreads();
        {
            const int row = t >> 1, cb = (t & 1) * 128;
            const float inv = minv[row];
            const float* src = E + row * 264 + cb;
            bf16* ph = g_P_hi + (growE + row) * TP + cb;
            bf16* pl = g_P_lo + (growE + row) * TP + cb;
#pragma unroll 8
            for (int j = 0; j < 64; j++) {
                bf16 h0, l0, h1, l1;
                split1(src[2 * j] * inv, h0, l0);
                split1(src[2 * j + 1] * inv, h1, l1);
                bf162 a; a.x = h0; a.y = h1; *(bf162*)(ph + 2 * j) = a;
                bf162 c2; c2.x = l0; c2.y = l1; *(bf162*)(pl + 2 * j) = c2;
            }
        }
    }
}

// ============ att_ln: C[64,512] = P[64,256] @ Kt[512,256]^T, + LayerNorm =====
// smem: Bh 0 (64K) | Bl 65536 (64K) | Ah 131072 (8K) | Al 139264 (8K)
//       gamma 147456 (4K) | beta 151552 (4K) | red 155648..157696
#define SMEM_ATT 157696
__global__ __launch_bounds__(256)
void att_ln(const float* __restrict__ gamma, const float* __restrict__ beta,
            float* __restrict__ att_out) {
    extern __shared__ char sm[];
    const uint32_t sb = s2u(sm);
    const int t = threadIdx.x, lane = t & 31, wid = t >> 5;
    const int wm = wid >> 2, wn = wid & 3;        // placeholder; real below
    const int WM = wid >> 1, WN = wid & 1;        // 4 x 2: warp tile 16 x 256
    (void)wm; (void)wn;
    const int bx = blockIdx.x, b = blockIdx.y;
    float* gamma_s = (float*)(sm + 147456);
    float* beta_s  = (float*)(sm + 151552);
    float* rS  = (float*)(sm + 155648);  // [2][64]
    float* rSS = (float*)(sm + 156160);  // [2][64]
    float* qS  = (float*)(sm + 156672);
    float* qSS = (float*)(sm + 156928);
    float* muA = (float*)(sm + 157184);
    float* rsA = (float*)(sm + 157440);
#pragma unroll
    for (int j = 0; j < 4; j++) {
        gamma_s[t + j * 256] = gamma[t + j * 256];
        beta_s[t + j * 256]  = beta[t + j * 256];
    }
    const size_t grow0 = (size_t)b * TF + (size_t)bx * 64;
    const size_t brow0 = (size_t)b * AD;

    float acc[32][4];
#pragma unroll
    for (int nt = 0; nt < 32; nt++)
#pragma unroll
        for (int j = 0; j < 4; j++) acc[nt][j] = 0.0f;

    for (int c = 0; c < 4; c++) {
        const int k0 = c * 64;
        ldt<512>(g_kt_hi, brow0, TP, k0, sb, t);
        ldt<512>(g_kt_lo, brow0, TP, k0, sb + 65536, t);
        ldt<64>(g_P_hi, grow0, TP, k0, sb + 131072, t);
        ldt<64>(g_P_lo, grow0, TP, k0, sb + 139264, t);
        cp_commit();
        cp_wait<0>();
        __syncthreads();
#pragma unroll
        for (int ks = 0; ks < 4; ks++) {
            uint32_t ah[4], al[4];
            {
                int row = WM * 16 + (lane & 15);
                int q = ks * 2 + (lane >> 4);
                uint32_t off = row * 128 + ((q ^ (row & 7)) << 4);
                ldm4(ah, sb + 131072 + off);
                ldm4(al, sb + 139264 + off);
            }
            const int g = lane >> 3, w = lane & 7;
#pragma unroll
            for (int qh = 0; qh < 4; qh++) {
                uint32_t bb[8][2];
#pragma unroll
                for (int np = 0; np < 4; np++) {
                    int ntl = qh * 8 + np * 2 + (g >> 1);
                    int row = WN * 256 + ntl * 8 + w;
                    int q = ks * 2 + (g & 1);
                    uint32_t off = row * 128 + ((q ^ (row & 7)) << 4);
                    uint32_t r4[4];
                    ldm4(r4, sb + off);
                    bb[np * 2][0] = r4[0]; bb[np * 2][1] = r4[1];
                    bb[np * 2 + 1][0] = r4[2]; bb[np * 2 + 1][1] = r4[3];
                }
#pragma unroll
                for (int nt = 0; nt < 8; nt++) {
                    mma16816(acc[qh * 8 + nt], ah, bb[nt][0], bb[nt][1]);
                    mma16816(acc[qh * 8 + nt], al, bb[nt][0], bb[nt][1]);
                }
#pragma unroll
                for (int np = 0; np < 4; np++) {
                    int ntl = qh * 8 + np * 2 + (g >> 1);
                    int row = WN * 256 + ntl * 8 + w;
                    int q = ks * 2 + (g & 1);
                    uint32_t off = row * 128 + ((q ^ (row & 7)) << 4);
                    uint32_t r4[4];
                    ldm4(r4, sb + 65536 + off);
                    bb[np * 2][0] = r4[0]; bb[np * 2][1] = r4[1];
                    bb[np * 2 + 1][0] = r4[2]; bb[np * 2 + 1][1] = r4[3];
                }
#pragma unroll
                for (int nt = 0; nt < 8; nt++)
                    mma16816(acc[qh * 8 + nt], ah, bb[nt][0], bb[nt][1]);
            }
        }
        __syncthreads();
    }

    // ---- LN reductions: att part ----
    float s0 = 0, ss0 = 0, s1 = 0, ss1 = 0;
#pragma unroll
    for (int nt = 0; nt < 32; nt++) {
        float a0 = acc[nt][0], a1 = acc[nt][1], a2 = acc[nt][2], a3 = acc[nt][3];
        s0 += a0 + a1; ss0 = fmaf(a0, a0, ss0); ss0 = fmaf(a1, a1, ss0);
        s1 += a2 + a3; ss1 = fmaf(a2, a2, ss1); ss1 = fmaf(a3, a3, ss1);
    }
#pragma unroll
    for (int o = 1; o < 4; o <<= 1) {
        s0 += __shfl_xor_sync(0xffffffffu, s0, o);
        ss0 += __shfl_xor_sync(0xffffffffu, ss0, o);
        s1 += __shfl_xor_sync(0xffffffffu, s1, o);
        ss1 += __shfl_xor_sync(0xffffffffu, ss1, o);
    }
    if ((lane & 3) == 0) {
        int r = WM * 16 + (lane >> 2);
        rS[WN * 64 + r] = s0;  rSS[WN * 64 + r] = ss0;
        rS[WN * 64 + r + 8] = s1; rSS[WN * 64 + r + 8] = ss1;
    }
    // ---- q part: 4 threads per row ----
    {
        const int row = t >> 2, qtr = t & 3;
        const float4* qp = (const float4*)(g_q + (grow0 + row) * AD + qtr * 128);
        float s = 0, ssq = 0;
#pragma unroll 8
        for (int u = 0; u < 32; u++) {
            float4 v = qp[u];
            s += v.x + v.y + v.z + v.w;
            ssq = fmaf(v.x, v.x, ssq); ssq = fmaf(v.y, v.y, ssq);
            ssq = fmaf(v.z, v.z, ssq); ssq = fmaf(v.w, v.w, ssq);
        }
#pragma unroll
        for (int o = 1; o < 4; o <<= 1) {
            s += __shfl_xor_sync(0xffffffffu, s, o);
            ssq += __shfl_xor_sync(0xffffffffu, ssq, o);
        }
        if ((t & 3) == 0) { qS[row] = s; qSS[row] = ssq; }
    }
    __syncthreads();
    if (t < 64) {
        float s = rS[t] + rS[64 + t] + qS[t];
        float ssq = rSS[t] + rSS[64 + t] + qSS[t];
        float mu = s * (1.0f / 1024.0f);
        float var = ssq * (1.0f / 1024.0f) - mu * mu;
        muA[t] = mu;
        rsA[t] = rsqrtf(var + 1e-5f);
    }
    __syncthreads();

    // ---- outputs ----
#pragma unroll
    for (int hh = 0; hh < 2; hh++) {
        const int rl = WM * 16 + (lane >> 2) + hh * 8;
        const float mu = muA[rl], rs = rsA[rl];
        float* orow = att_out + (grow0 + rl) * 1024;
#pragma unroll
        for (int nt = 0; nt < 32; nt++) {
            const int cl = WN * 256 + nt * 8 + (lane & 3) * 2;
            float v0 = (acc[nt][hh * 2] - mu) * rs * gamma_s[cl] + beta_s[cl];
            float v1 = (acc[nt][hh * 2 + 1] - mu) * rs * gamma_s[cl + 1] + beta_s[cl + 1];
            *(float2*)(orow + cl) = make_float2(v0, v1);
        }
    }
    {
        const int row = t >> 2, qtr = t & 3;
        const float mu = muA[row], rs = rsA[row];
        const float4* qp = (const float4*)(g_q + (grow0 + row) * AD + qtr * 128);
        float* orow = att_out + (grow0 + row) * 1024 + 512 + qtr * 128;
#pragma unroll 8
        for (int u = 0; u < 32; u++) {
            float4 v = qp[u];
            const int c = 512 + qtr * 128 + u * 4;
            float4 o;
            o.x = (v.x - mu) * rs * gamma_s[c] + beta_s[c];
            o.y = (v.y - mu) * rs * gamma_s[c + 1] + beta_s[c + 1];
            o.z = (v.z - mu) * rs * gamma_s[c + 2] + beta_s[c + 2];
            o.w = (v.w - mu) * rs * gamma_s[c + 3] + beta_s[c + 3];
            *(float4*)(orow + u * 4) = o;
        }
    }
}

// ---------------- prep kernels ----------------
__global__ void split_k(const float* __restrict__ in, bf16* __restrict__ hi,
                        bf16* __restrict__ lo, size_t n4) {
    size_t i = (size_t)blockIdx.x * blockDim.x + threadIdx.x;
    if (i >= n4) return;
    float4 v = ((const float4*)in)[i];
    bf16 h0, h1, h2, h3, l0, l1, l2, l3;
    split1(v.x, h0, l0); split1(v.y, h1, l1);
    split1(v.z, h2, l2); split1(v.w, h3, l3);
    bf162 a, b;
    a.x = h0; a.y = h1; b.x = h2; b.y = h3;
    ((bf162*)hi)[i * 2] = a; ((bf162*)hi)[i * 2 + 1] = b;
    a.x = l0; a.y = l1; b.x = l2; b.y = l3;
    ((bf162*)lo)[i * 2] = a; ((bf162*)lo)[i * 2 + 1] = b;
}
__global__ void tsplit_k(const float* __restrict__ W, bf16* __restrict__ hiT,
                         bf16* __restrict__ loT, int K, int N) {
    __shared__ float tile[32][33];
    const int n0 = blockIdx.x * 32, k0 = blockIdx.y * 32;
    for (int r = threadIdx.y; r < 32; r += 8)
        tile[r][threadIdx.x] = W[(size_t)(k0 + r) * N + n0 + threadIdx.x];
    __syncthreads();
    for (int r = threadIdx.y; r < 32; r += 8) {
        float v = tile[threadIdx.x][r];
        bf16 h, l;
        split1(v, h, l);
        hiT[(size_t)(n0 + r) * K + k0 + threadIdx.x] = h;
        loT[(size_t)(n0 + r) * K + k0 + threadIdx.x] = l;
    }
}

// ---------------------------------------------------------------------------
extern "C" void kernel_launch(void* const* d_in, const int* in_sizes, int n_in,
                              void* d_out, int out_size) {
    const float* frame = (const float*)d_in[0];
    const float* phn   = (const float*)d_in[1];
    const int*   amask = (const int*)  d_in[2];
    const float* Wq    = (const float*)d_in[3];
    const float* bq    = (const float*)d_in[4];
    const float* Wk    = (const float*)d_in[5];
    const float* bk    = (const float*)d_in[6];
    const float* gamma = (const float*)d_in[7];
    const float* beta  = (const float*)d_in[8];

    float* out        = (float*)d_out;
    float* att_out    = out;
    float* energy_out = out + ((size_t)out_size - (size_t)BB * TF * TP);

    cudaFuncSetAttribute(gemm128<0>, cudaFuncAttributeMaxDynamicSharedMemorySize, SMEM_G);
    cudaFuncSetAttribute(gemm128<1>, cudaFuncAttributeMaxDynamicSharedMemorySize, SMEM_G);
    cudaFuncSetAttribute(gemm128<2>, cudaFuncAttributeMaxDynamicSharedMemorySize, SMEM_G);
    cudaFuncSetAttribute(att_ln, cudaFuncAttributeMaxDynamicSharedMemorySize, SMEM_ATT);

    bf16 *fh, *fl, *ph_, *pl_, *wqh, *wql, *wkh, *wkl, *qh, *ql, *kh, *kl;
    cudaGetSymbolAddress((void**)&fh, g_f_hi);
    cudaGetSymbolAddress((void**)&fl, g_f_lo);
    cudaGetSymbolAddress((void**)&ph_, g_p_hi);
    cudaGetSymbolAddress((void**)&pl_, g_p_lo);
    cudaGetSymbolAddress((void**)&wqh, g_wqt_hi);
    cudaGetSymbolAddress((void**)&wql, g_wqt_lo);
    cudaGetSymbolAddress((void**)&wkh, g_wkt_hi);
    cudaGetSymbolAddress((void**)&wkl, g_wkt_lo);
    cudaGetSymbolAddress((void**)&qh, g_q_hi);
    cudaGetSymbolAddress((void**)&ql, g_q_lo);
    cudaGetSymbolAddress((void**)&kh, g_k_hi);
    cudaGetSymbolAddress((void**)&kl, g_k_lo);

    {
        size_t n4 = (size_t)BB * TF * FD / 4;
        split_k<<<(unsigned)(n4 / 256), 256>>>(frame, fh, fl, n4);
    }
    {
        size_t n4 = (size_t)BB * TP * PD / 4;
        split_k<<<(unsigned)(n4 / 256), 256>>>(phn, ph_, pl_, n4);
    }
    tsplit_k<<<dim3(AD / 32, FD / 32), dim3(32, 8)>>>(Wq, wqh, wql, FD, AD);
    tsplit_k<<<dim3(AD / 32, PD / 32), dim3(32, 8)>>>(Wk, wkh, wkl, PD, AD);

    // projections (K proj also emits K^T)
    gemm128<1><<<dim3(2, 64), 256, SMEM_G>>>(ph_, pl_, PD, wkh, wkl, PD, PD, bk, nullptr);
    gemm128<0><<<dim3(2, 512), 256, SMEM_G>>>(fh, fl, FD, wqh, wql, FD, FD, bq, nullptr);

    // energy + mask + softmax (+ P split)
    gemm128<2><<<dim3(16, 32), 256, SMEM_G>>>(qh, ql, AD, kh, kl, AD, AD, amask, energy_out);

    // att + LayerNorm
    att_ln<<<dim3(32, 32), 256, SMEM_ATT>>>(gamma, beta, att_out);
}

// round 6
// speedup vs baseline: 1.1227x; 1.1227x over previous
#include <cuda_runtime.h>
#include <cuda_bf16.h>
#include <math.h>
#include <stdint.h>

#define BB 32
#define TF 2048
#define TP 256
#define FD 768
#define PD 512
#define AD 512
typedef __nv_bfloat16 bf16;
typedef __nv_bfloat162 bf162;

// ---------------- device scratch ----------------
__device__ float g_q[(size_t)BB * TF * AD];
__device__ float g_att[(size_t)BB * TF * AD];
__device__ bf16 g_f_hi[(size_t)BB * TF * FD], g_f_lo[(size_t)BB * TF * FD];
__device__ bf16 g_p_hi[(size_t)BB * TP * PD], g_p_lo[(size_t)BB * TP * PD];
__device__ bf16 g_wqt_hi[AD * FD], g_wqt_lo[AD * FD];
__device__ bf16 g_wkt_hi[AD * PD], g_wkt_lo[AD * PD];
__device__ bf16 g_q_hi[(size_t)BB * TF * AD], g_q_lo[(size_t)BB * TF * AD];
__device__ bf16 g_k_hi[(size_t)BB * TP * AD], g_k_lo[(size_t)BB * TP * AD];
__device__ bf16 g_kt_hi[(size_t)BB * AD * TP], g_kt_lo[(size_t)BB * AD * TP];
__device__ bf16 g_P_hi[(size_t)BB * TF * TP], g_P_lo[(size_t)BB * TF * TP];

// ---------------- helpers ----------------
__device__ __forceinline__ uint32_t s2u(const void* p) {
    uint32_t a;
    asm("{ .reg .u64 t; cvta.to.shared.u64 t, %1; cvt.u32.u64 %0, t; }"
        : "=r"(a) : "l"(p));
    return a;
}
__device__ __forceinline__ void split1(float v, bf16& h, bf16& l) {
    h = __float2bfloat16_rn(v);
    l = __float2bfloat16_rn(v - __bfloat162float(h));
}
__device__ __forceinline__ void cp16(uint32_t dst, const void* src) {
    asm volatile("cp.async.cg.shared.global [%0], [%1], 16;" :: "r"(dst), "l"(src));
}
__device__ __forceinline__ void cp_commit() { asm volatile("cp.async.commit_group;"); }
template <int N>
__device__ __forceinline__ void cp_wait() {
    asm volatile("cp.async.wait_group %0;" :: "n"(N));
}
__device__ __forceinline__ void ldm4(uint32_t* r, uint32_t addr) {
    asm volatile("ldmatrix.sync.aligned.m8n8.x4.shared.b16 {%0,%1,%2,%3}, [%4];"
                 : "=r"(r[0]), "=r"(r[1]), "=r"(r[2]), "=r"(r[3]) : "r"(addr));
}
__device__ __forceinline__ void mma16816(float* c, const uint32_t* a,
                                         uint32_t b0, uint32_t b1) {
    asm volatile("mma.sync.aligned.m16n8k16.row.col.f32.bf16.bf16.f32 "
                 "{%0,%1,%2,%3}, {%4,%5,%6,%7}, {%8,%9}, {%0,%1,%2,%3};"
                 : "+f"(c[0]), "+f"(c[1]), "+f"(c[2]), "+f"(c[3])
                 : "r"(a[0]), "r"(a[1]), "r"(a[2]), "r"(a[3]), "r"(b0), "r"(b1));
}
// FFMA-only exp; valid for x <= ~80, clamps hard-underflow to ~0.
__device__ __forceinline__ float fexp(float x) {
    float y = fmaxf(x * 1.44269504f, -125.0f);
    float i = rintf(y);
    float f = y - i;
    float p = 1.3333558146e-3f;
    p = fmaf(p, f, 9.6181291076e-3f);
    p = fmaf(p, f, 5.5504108664e-2f);
    p = fmaf(p, f, 2.4022650696e-1f);
    p = fmaf(p, f, 6.9314718056e-1f);
    p = fmaf(p, f, 1.0f);
    float s = __int_as_float(((int)i + 127) << 23);
    return p * s;
}
// cp.async [ROWS x 64]bf16 K-major tile into XOR-swizzled smem; 512 threads
template <int ROWS>
__device__ __forceinline__ void ldt(const bf16* __restrict__ src, size_t row0,
                                    int ld, int k0, uint32_t dst, int t) {
#pragma unroll
    for (int it = 0; it < ROWS / 64; it++) {
        int u = it * 512 + t;
        int row = u >> 3, q = u & 7;
        cp16(dst + row * 128 + ((q ^ (row & 7)) << 4),
             src + (row0 + row) * (size_t)ld + k0 + q * 8);
    }
}

// ======= gemm_tc: C[256,128] = A[256,K] @ B[128,K]^T, 512 thr, 16 warps =====
// stage: Ah 32K | Al 32K | Bh 16K | Bl 16K  (96K); double buffered.
// MODE: 0 projQ, 1 projK (+K^T), 2 energy(+mask), 3 att(->g_att)
#define STG 98304
#define GEMM_SMEM (2 * STG)
template <int MODE>
__global__ __launch_bounds__(512, 1)
void gemm_tc(const bf16* __restrict__ Ah, const bf16* __restrict__ Al, int lda,
             int sA, const bf16* __restrict__ Bh, const bf16* __restrict__ Bl,
             int ldb, int sB, int K, const void* __restrict__ aux,
             float* __restrict__ outp) {
    extern __shared__ char sm[];
    const uint32_t sbase = s2u(sm);
    const int t = threadIdx.x, lane = t & 31, wid = t >> 5;
    const int wm = wid >> 1, wn = wid & 1;  // 8 x 2 warps, warp tile 32 x 64
    const int b = blockIdx.z;
    const size_t arow0 = (size_t)b * sA + (size_t)blockIdx.y * 256;
    const size_t brow0 = (size_t)b * sB + (size_t)blockIdx.x * 128;
    const int NC = K / 64;

    float acc[2][8][4];
#pragma unroll
    for (int mt = 0; mt < 2; mt++)
#pragma unroll
        for (int nt = 0; nt < 8; nt++)
#pragma unroll
            for (int j = 0; j < 4; j++) acc[mt][nt][j] = 0.0f;

    {
        uint32_t s0 = sbase;
        ldt<256>(Ah, arow0, lda, 0, s0, t);
        ldt<256>(Al, arow0, lda, 0, s0 + 32768, t);
        ldt<128>(Bh, brow0, ldb, 0, s0 + 65536, t);
        ldt<128>(Bl, brow0, ldb, 0, s0 + 81920, t);
        cp_commit();
    }
    for (int c = 0; c < NC; c++) {
        if (c + 1 < NC) {
            uint32_t sn = sbase + ((c + 1) & 1) * STG;
            const int k0 = (c + 1) * 64;
            ldt<256>(Ah, arow0, lda, k0, sn, t);
            ldt<256>(Al, arow0, lda, k0, sn + 32768, t);
            ldt<128>(Bh, brow0, ldb, k0, sn + 65536, t);
            ldt<128>(Bl, brow0, ldb, k0, sn + 81920, t);
            cp_commit();
            cp_wait<1>();
        } else {
            cp_wait<0>();
        }
        __syncthreads();
        const uint32_t s = sbase + (c & 1) * STG;
        const uint32_t Ahb = s, Alb = s + 32768;
        const uint32_t Bhb = s + 65536, Blb = s + 81920;
#pragma unroll
        for (int ks = 0; ks < 4; ks++) {
            uint32_t ah[2][4], al[2][4], bh[8][2], bl[8][2];
#pragma unroll
            for (int mt = 0; mt < 2; mt++) {
                int row = wm * 32 + mt * 16 + (lane & 15);
                int q = ks * 2 + (lane >> 4);
                uint32_t off = row * 128 + ((q ^ (row & 7)) << 4);
                ldm4(ah[mt], Ahb + off);
                ldm4(al[mt], Alb + off);
            }
            const int g = lane >> 3, w = lane & 7;
#pragma unroll
            for (int np = 0; np < 4; np++) {
                int ntl = np * 2 + (g >> 1);
                int row = wn * 64 + ntl * 8 + w;
                int q = ks * 2 + (g & 1);
                uint32_t off = row * 128 + ((q ^ (row & 7)) << 4);
                uint32_t r4[4];
                ldm4(r4, Bhb + off);
                bh[np * 2][0] = r4[0]; bh[np * 2][1] = r4[1];
                bh[np * 2 + 1][0] = r4[2]; bh[np * 2 + 1][1] = r4[3];
                ldm4(r4, Blb + off);
                bl[np * 2][0] = r4[0]; bl[np * 2][1] = r4[1];
                bl[np * 2 + 1][0] = r4[2]; bl[np * 2 + 1][1] = r4[3];
            }
#pragma unroll
            for (int mt = 0; mt < 2; mt++)
#pragma unroll
                for (int nt = 0; nt < 8; nt++) {
                    mma16816(acc[mt][nt], ah[mt], bh[nt][0], bh[nt][1]);
                    mma16816(acc[mt][nt], ah[mt], bl[nt][0], bl[nt][1]);
                    mma16816(acc[mt][nt], al[mt], bh[nt][0], bh[nt][1]);
                }
        }
        __syncthreads();
    }

    // ---------------- epilogue ----------------
#pragma unroll
    for (int mt = 0; mt < 2; mt++)
#pragma unroll
        for (int h = 0; h < 2; h++) {
            const int rl = wm * 32 + mt * 16 + (lane >> 2) + h * 8;
#pragma unroll
            for (int nt = 0; nt < 8; nt++) {
                const int cl = wn * 64 + nt * 8 + (lane & 3) * 2;
                float v0 = acc[mt][nt][h * 2];
                float v1 = acc[mt][nt][h * 2 + 1];
                if (MODE == 0 || MODE == 1) {
                    const float* bias = (const float*)aux;
                    const size_t gr = (size_t)blockIdx.y * 256 + rl;
                    const int gc = blockIdx.x * 128 + cl;
                    v0 += bias[gc];
                    v1 += bias[gc + 1];
                    bf16 h0, l0, h1, l1;
                    split1(v0, h0, l0);
                    split1(v1, h1, l1);
                    bf162 ph; ph.x = h0; ph.y = h1;
                    bf162 pl; pl.x = l0; pl.y = l1;
                    if (MODE == 0) {
                        *(float2*)&g_q[gr * AD + gc] = make_float2(v0, v1);
                        *(bf162*)&g_q_hi[gr * AD + gc] = ph;
                        *(bf162*)&g_q_lo[gr * AD + gc] = pl;
                    } else {
                        *(bf162*)&g_k_hi[gr * AD + gc] = ph;
                        *(bf162*)&g_k_lo[gr * AD + gc] = pl;
                        const int bb = (int)(gr >> 8), p = (int)(gr & 255);
                        g_kt_hi[((size_t)bb * AD + gc) * TP + p] = h0;
                        g_kt_lo[((size_t)bb * AD + gc) * TP + p] = l0;
                        g_kt_hi[((size_t)bb * AD + gc + 1) * TP + p] = h1;
                        g_kt_lo[((size_t)bb * AD + gc + 1) * TP + p] = l1;
                    }
                } else if (MODE == 2) {
                    const int* am = (const int*)aux;
                    const int mrow = blockIdx.y * 256 + rl;
                    const int gcol = blockIdx.x * 128 + cl;
                    v0 += (1.0f - (float)am[b * TP + gcol]) * (-1000.0f);
                    v1 += (1.0f - (float)am[b * TP + gcol + 1]) * (-1000.0f);
                    *(float2*)&outp[((size_t)b * TF + mrow) * TP + gcol] =
                        make_float2(v0, v1);
                } else {
                    const int mrow = blockIdx.y * 256 + rl;
                    const int gcol = blockIdx.x * 128 + cl;
                    *(float2*)&g_att[((size_t)b * TF + mrow) * AD + gcol] =
                        make_float2(v0, v1);
                }
            }
        }
}

// ---------------- pointwise kernels ----------------
__global__ void split_k(const float* __restrict__ in, bf16* __restrict__ hi,
                        bf16* __restrict__ lo, size_t n4) {
    size_t i = (size_t)blockIdx.x * blockDim.x + threadIdx.x;
    if (i >= n4) return;
    float4 v = ((const float4*)in)[i];
    bf16 h0, h1, h2, h3, l0, l1, l2, l3;
    split1(v.x, h0, l0); split1(v.y, h1, l1);
    split1(v.z, h2, l2); split1(v.w, h3, l3);
    bf162 a, b;
    a.x = h0; a.y = h1; b.x = h2; b.y = h3;
    ((bf162*)hi)[i * 2] = a; ((bf162*)hi)[i * 2 + 1] = b;
    a.x = l0; a.y = l1; b.x = l2; b.y = l3;
    ((bf162*)lo)[i * 2] = a; ((bf162*)lo)[i * 2 + 1] = b;
}
__global__ void tsplit_k(const float* __restrict__ W, bf16* __restrict__ hiT,
                         bf16* __restrict__ loT, int K, int N) {
    __shared__ float tile[32][33];
    const int n0 = blockIdx.x * 32, k0 = blockIdx.y * 32;
    for (int r = threadIdx.y; r < 32; r += 8)
        tile[r][threadIdx.x] = W[(size_t)(k0 + r) * N + n0 + threadIdx.x];
    __syncthreads();
    for (int r = threadIdx.y; r < 32; r += 8) {
        float v = tile[threadIdx.x][r];
        bf16 h, l;
        split1(v, h, l);
        hiT[(size_t)(n0 + r) * K + k0 + threadIdx.x] = h;
        loT[(size_t)(n0 + r) * K + k0 + threadIdx.x] = l;
    }
}
__global__ void transpose_bf(const bf16* __restrict__ in, bf16* __restrict__ out) {
    __shared__ bf16 tile[32][33];
    const int r0 = blockIdx.y * 32, c0 = blockIdx.x * 32;
    for (int r = threadIdx.y; r < 32; r += 8)
        tile[r][threadIdx.x] = in[(size_t)(r0 + r) * AD + c0 + threadIdx.x];
    __syncthreads();
    const int b = r0 >> 8, p0 = r0 & 255;
    for (int r = threadIdx.y; r < 32; r += 8)
        out[((size_t)b * AD + c0 + r) * TP + p0 + threadIdx.x] = tile[threadIdx.x][r];
}
__global__ __launch_bounds__(256)
void softmax_k(const float* __restrict__ energy) {
    const int lane = threadIdx.x & 31, wid = threadIdx.x >> 5;
    const size_t row = (size_t)blockIdx.x * 8 + wid;
    const float* e = energy + row * TP + lane * 8;
    float v[8];
    *(float4*)&v[0] = *(const float4*)(e);
    *(float4*)&v[4] = *(const float4*)(e + 4);
    float mx = v[0];
#pragma unroll
    for (int j = 1; j < 8; j++) mx = fmaxf(mx, v[j]);
#pragma unroll
    for (int o = 16; o > 0; o >>= 1)
        mx = fmaxf(mx, __shfl_xor_sync(0xffffffffu, mx, o));
    float s = 0.0f;
#pragma unroll
    for (int j = 0; j < 8; j++) { v[j] = fexp(v[j] - mx); s += v[j]; }
#pragma unroll
    for (int o = 16; o > 0; o >>= 1)
        s += __shfl_xor_sync(0xffffffffu, s, o);
    const float inv = 1.0f / s;
    bf16* ph = g_P_hi + row * TP + lane * 8;
    bf16* pl = g_P_lo + row * TP + lane * 8;
#pragma unroll
    for (int j = 0; j < 8; j += 2) {
        bf16 h0, l0, h1, l1;
        split1(v[j] * inv, h0, l0);
        split1(v[j + 1] * inv, h1, l1);
        bf162 a; a.x = h0; a.y = h1; *(bf162*)(ph + j) = a;
        bf162 c; c.x = l0; c.y = l1; *(bf162*)(pl + j) = c;
    }
}
__global__ __launch_bounds__(256)
void ln_k(const float* __restrict__ gamma, const float* __restrict__ beta,
          float* __restrict__ att_out) {
    const int lane = threadIdx.x & 31, wid = threadIdx.x >> 5;
    const size_t row = (size_t)blockIdx.x * 8 + wid;
    const float4* arow = (const float4*)(g_att + row * AD) + lane * 4;
    const float4* qrow = (const float4*)(g_q + row * AD) + lane * 4;
    float4 av[4], qv[4];
    float s = 0.0f, ss = 0.0f;
#pragma unroll
    for (int u = 0; u < 4; u++) {
        av[u] = arow[u];
        qv[u] = qrow[u];
        s += av[u].x + av[u].y + av[u].z + av[u].w;
        s += qv[u].x + qv[u].y + qv[u].z + qv[u].w;
        ss = fmaf(av[u].x, av[u].x, ss); ss = fmaf(av[u].y, av[u].y, ss);
        ss = fmaf(av[u].z, av[u].z, ss); ss = fmaf(av[u].w, av[u].w, ss);
        ss = fmaf(qv[u].x, qv[u].x, ss); ss = fmaf(qv[u].y, qv[u].y, ss);
        ss = fmaf(qv[u].z, qv[u].z, ss); ss = fmaf(qv[u].w, qv[u].w, ss);
    }
#pragma unroll
    for (int o = 16; o > 0; o >>= 1) {
        s  += __shfl_xor_sync(0xffffffffu, s, o);
        ss += __shfl_xor_sync(0xffffffffu, ss, o);
    }
    const float mu = s * (1.0f / 1024.0f);
    const float var = ss * (1.0f / 1024.0f) - mu * mu;
    const float rs = rsqrtf(var + 1e-5f);
    float* orow = att_out + row * 1024;
#pragma unroll
    for (int u = 0; u < 4; u++) {
        int c = lane * 16 + u * 4;
        float4 g = *(const float4*)(gamma + c);
        float4 be = *(const float4*)(beta + c);
        float4 o;
        o.x = (av[u].x - mu) * rs * g.x + be.x;
        o.y = (av[u].y - mu) * rs * g.y + be.y;
        o.z = (av[u].z - mu) * rs * g.z + be.z;
        o.w = (av[u].w - mu) * rs * g.w + be.w;
        *(float4*)(orow + c) = o;
        int c2 = AD + c;
        g = *(const float4*)(gamma + c2);
        be = *(const float4*)(beta + c2);
        o.x = (qv[u].x - mu) * rs * g.x + be.x;
        o.y = (qv[u].y - mu) * rs * g.y + be.y;
        o.z = (qv[u].z - mu) * rs * g.z + be.z;
        o.w = (qv[u].w - mu) * rs * g.w + be.w;
        *(float4*)(orow + c2) = o;
    }
}

// ---------------------------------------------------------------------------
extern "C" void kernel_launch(void* const* d_in, const int* in_sizes, int n_in,
                              void* d_out, int out_size) {
    const float* frame = (const float*)d_in[0];
    const float* phn   = (const float*)d_in[1];
    const int*   amask = (const int*)  d_in[2];
    const float* Wq    = (const float*)d_in[3];
    const float* bq    = (const float*)d_in[4];
    const float* Wk    = (const float*)d_in[5];
    const float* bk    = (const float*)d_in[6];
    const float* gamma = (const float*)d_in[7];
    const float* beta  = (const float*)d_in[8];

    float* out        = (float*)d_out;
    float* att_out    = out;
    float* energy_out = out + ((size_t)out_size - (size_t)BB * TF * TP);

    cudaFuncSetAttribute(gemm_tc<0>, cudaFuncAttributeMaxDynamicSharedMemorySize, GEMM_SMEM);
    cudaFuncSetAttribute(gemm_tc<1>, cudaFuncAttributeMaxDynamicSharedMemorySize, GEMM_SMEM);
    cudaFuncSetAttribute(gemm_tc<2>, cudaFuncAttributeMaxDynamicSharedMemorySize, GEMM_SMEM);
    cudaFuncSetAttribute(gemm_tc<3>, cudaFuncAttributeMaxDynamicSharedMemorySize, GEMM_SMEM);

    bf16 *fh, *fl, *ph_, *pl_, *wqh, *wql, *wkh, *wkl;
    bf16 *qh, *ql, *kh, *kl, *kth, *ktl, *Ph, *Pl;
    cudaGetSymbolAddress((void**)&fh, g_f_hi);
    cudaGetSymbolAddress((void**)&fl, g_f_lo);
    cudaGetSymbolAddress((void**)&ph_, g_p_hi);
    cudaGetSymbolAddress((void**)&pl_, g_p_lo);
    cudaGetSymbolAddress((void**)&wqh, g_wqt_hi);
    cudaGetSymbolAddress((void**)&wql, g_wqt_lo);
    cudaGetSymbolAddress((void**)&wkh, g_wkt_hi);
    cudaGetSymbolAddress((void**)&wkl, g_wkt_lo);
    cudaGetSymbolAddress((void**)&qh, g_q_hi);
    cudaGetSymbolAddress((void**)&ql, g_q_lo);
    cudaGetSymbolAddress((void**)&kh, g_k_hi);
    cudaGetSymbolAddress((void**)&kl, g_k_lo);
    cudaGetSymbolAddress((void**)&kth, g_kt_hi);
    cudaGetSymbolAddress((void**)&ktl, g_kt_lo);
    cudaGetSymbolAddress((void**)&Ph, g_P_hi);
    cudaGetSymbolAddress((void**)&Pl, g_P_lo);

    {
        size_t n4 = (size_t)BB * TF * FD / 4;
        split_k<<<(unsigned)(n4 / 256), 256>>>(frame, fh, fl, n4);
    }
    {
        size_t n4 = (size_t)BB * TP * PD / 4;
        split_k<<<(unsigned)(n4 / 256), 256>>>(phn, ph_, pl_, n4);
    }
    tsplit_k<<<dim3(AD / 32, FD / 32), dim3(32, 8)>>>(Wq, wqh, wql, FD, AD);
    tsplit_k<<<dim3(AD / 32, PD / 32), dim3(32, 8)>>>(Wk, wkh, wkl, PD, AD);

    // K projection: [8192,512] = phn @ Wk^T(+bk), also emits K^T
    gemm_tc<1><<<dim3(4, 32, 1), 512, GEMM_SMEM>>>(ph_, pl_, PD, 0, wkh, wkl,
                                                   PD, 0, PD, bk, nullptr);
    // Q projection: [65536,512] = frame @ Wq^T(+bq)
    gemm_tc<0><<<dim3(4, 256, 1), 512, GEMM_SMEM>>>(fh, fl, FD, 0, wqh, wql,
                                                    FD, 0, FD, bq, nullptr);

    // energy = q @ k^T + mask  (batched)
    gemm_tc<2><<<dim3(2, 8, BB), 512, GEMM_SMEM>>>(qh, ql, AD, TF, kh, kl,
                                                   AD, TP, AD, amask, energy_out);

    // softmax rows -> P hi/lo
    softmax_k<<<BB * TF / 8, 256>>>(energy_out);

    // att = P @ k  (batched, via K^T rows)
    gemm_tc<3><<<dim3(4, 8, BB), 512, GEMM_SMEM>>>(Ph, Pl, TP, TF, kth, ktl,
                                                   TP, AD, TP, nullptr, nullptr);

    // LayerNorm over concat(att, q)
    ln_k<<<BB * TF / 8, 256>>>(gamma, beta, att_out);
}